// round 10
// baseline (speedup 1.0000x reference)
#include <cuda_runtime.h>
#include <cuda_bf16.h>
#include <cstddef>
#include <math.h>

#define NDIM 8192
#define NGROUP 32
#define GSIZE 256
#define INV_TAU 10.0f
#define TILE 64
#define NT (NDIM / TILE)          // 128 tiles per side
#define NPAIR (NT * (NT + 1) / 2) // 8256 tile pairs (I <= J)
#define GRID 688                  // 8256 = 688*12 exactly; 688 <= 148*5 resident

// Per-(row, group) softmax normalizer: 1 / sum(exp(x * 10)), NO max shift.
// Safe: x ~ N(0,1) so x*10 < ~60 << 88.7 (fp32 exp overflow).
__device__ float g_r[NDIM * NGROUP];

// Monotonic device-wide barrier ticket counter. Never reset: each launch
// adds exactly GRID, and each block waits for the end of ITS OWN launch's
// arrival window (goal = (ticket/GRID + 1) * GRID), so the barrier is
// re-entrant across graph replays with zero shared-state cleanup.
__device__ unsigned g_bar;

// ---------------------------------------------------------------------------
// Fused persistent kernel, 688 blocks x 256 threads, all co-resident
// (launch_bounds(256,5): regs<=51, smem 17.2KB -> occ 5/SM -> 740 slots).
//
// Phase 1 (stats): grid-stride over rows. Per row, warp w owns a 4KB span =
// groups 4w..4w+3; each LDG.128 covers a fully dense 512B stretch. Four
// independent 5-shfl butterflies; one float4 store of 4 reciprocals.
// Grid-striding amortizes block setup over ~12 rows and removes the wave
// transitions that pinned the standalone stats kernel at ~49us.
//
// Device barrier, then Phase 2 (pairs): grid-stride over tile pairs (I,J),
// I<=J, 12 iterations per block exactly. A tile in registers; B staged
// transposed in smem; e overwrites b in place; symmetric double store.
//   e(i,j) = (exp(a*10) * rA[i]) * (exp(b*10) * rB[j])
// g_r is read with __ldcg (L2) — L1 is not coherent across SMs.
// ---------------------------------------------------------------------------
__global__ __launch_bounds__(256, 5) void fused_kernel(const float* __restrict__ S,
                                                       float* __restrict__ O) {
    __shared__ float sM[TILE][TILE + 1];    // b-transposed, then e in place
    __shared__ float rA[TILE], rB[TILE];

    const int t    = threadIdx.x;
    const int warp = t >> 5;
    const int lane = t & 31;

    // ---------------- Phase 1: stats ----------------
    {
        const int wbase = warp * (4 * GSIZE);
        for (int row = blockIdx.x; row < NDIM; row += GRID) {
            const float* p = S + (size_t)row * NDIM + wbase + lane * 4;

            float4 v[8];
#pragma unroll
            for (int k = 0; k < 8; ++k)
                v[k] = *(const float4*)(p + k * 128);   // dense 512B per instr

            const int d0 = row - (wbase + lane * 4);

            float part[4];
#pragma unroll
            for (int gg = 0; gg < 4; ++gg) {
                float s = 0.f;
#pragma unroll
                for (int h = 0; h < 2; ++h) {
                    const int k = 2 * gg + h;
                    const int kb = k * 128;
                    float ex = (d0 == kb + 0) ? 0.f : __expf(v[k].x * INV_TAU);
                    float ey = (d0 == kb + 1) ? 0.f : __expf(v[k].y * INV_TAU);
                    float ez = (d0 == kb + 2) ? 0.f : __expf(v[k].z * INV_TAU);
                    float ew = (d0 == kb + 3) ? 0.f : __expf(v[k].w * INV_TAU);
                    s += (ex + ey) + (ez + ew);
                }
                part[gg] = s;
            }

#pragma unroll
            for (int o = 16; o > 0; o >>= 1) {
#pragma unroll
                for (int gg = 0; gg < 4; ++gg)
                    part[gg] += __shfl_xor_sync(0xffffffffu, part[gg], o);
            }

            if (lane == 0) {
                float4 r;
                r.x = 1.0f / part[0];
                r.y = 1.0f / part[1];
                r.z = 1.0f / part[2];
                r.w = 1.0f / part[3];
                *(float4*)&g_r[row * NGROUP + warp * 4] = r;
            }
        }
    }

    // ---------------- Device-wide barrier ----------------
    __syncthreads();
    if (t == 0) {
        __threadfence();                                // publish g_r
        const unsigned my   = atomicAdd(&g_bar, 1u);
        const unsigned goal = (my / GRID + 1u) * GRID;  // end of this launch's window
        while (*(volatile unsigned*)&g_bar < goal) { }  // all co-resident: safe
    }
    __syncthreads();

    // ---------------- Phase 2: tile pairs ----------------
    for (int Lr = blockIdx.x; Lr < NPAIR; Lr += GRID) {
        const int L = NPAIR - 1 - Lr;
        int J = (int)((sqrtf(8.0f * (float)L + 1.0f) - 1.0f) * 0.5f);
        while ((J + 1) * (J + 2) / 2 <= L) ++J;
        while (J * (J + 1) / 2 > L) --J;
        const int I = L - J * (J + 1) / 2;

        const int tx = t & 15, ty = t >> 4;
        const int rowA = I * TILE, colA = J * TILE;
        const int c0 = tx * 4;

        // Front-batched global loads (issue before the smem-guard sync).
        float4 a4[4], b4[4];
#pragma unroll
        for (int k = 0; k < 4; ++k) {
            const int r = ty + 16 * k;
            a4[k] = __ldcs((const float4*)(S + (size_t)(rowA + r) * NDIM + colA + c0));
            b4[k] = __ldcs((const float4*)(S + (size_t)(colA + r) * NDIM + rowA + c0));
        }

        __syncthreads();   // previous iteration's phase-B readers are done

        if (t < TILE) {
            rA[t] = __ldcg(&g_r[(size_t)(rowA + t) * NGROUP + (colA >> 8)]);
        } else if (t < 2 * TILE) {
            const int tt = t - TILE;
            rB[tt] = __ldcg(&g_r[(size_t)(colA + tt) * NGROUP + (rowA >> 8)]);
        }

        // Scatter B transposed into smem: sM[x][y] = S[colA+y][rowA+x].
#pragma unroll
        for (int k = 0; k < 4; ++k) {
            const int r = ty + 16 * k;
            sM[c0 + 0][r] = b4[k].x;
            sM[c0 + 1][r] = b4[k].y;
            sM[c0 + 2][r] = b4[k].z;
            sM[c0 + 3][r] = b4[k].w;
        }
        __syncthreads();

        const float4 rB4 = *(const float4*)&rB[c0];

        // Compute: store tile (I,J), overwrite b with e in place.
#pragma unroll
        for (int k = 0; k < 4; ++k) {
            const int i = ty + 16 * k;
            const float ra = rA[i];

            float4 ev;
            ev.x = (__expf(a4[k].x * INV_TAU) * ra) * (__expf(sM[i][c0 + 0] * INV_TAU) * rB4.x);
            ev.y = (__expf(a4[k].y * INV_TAU) * ra) * (__expf(sM[i][c0 + 1] * INV_TAU) * rB4.y);
            ev.z = (__expf(a4[k].z * INV_TAU) * ra) * (__expf(sM[i][c0 + 2] * INV_TAU) * rB4.z);
            ev.w = (__expf(a4[k].w * INV_TAU) * ra) * (__expf(sM[i][c0 + 3] * INV_TAU) * rB4.w);

            if (I == J) {   // diagonal of the full matrix sits in this tile
                if (i == c0 + 0) ev.x = 0.f;
                if (i == c0 + 1) ev.y = 0.f;
                if (i == c0 + 2) ev.z = 0.f;
                if (i == c0 + 3) ev.w = 0.f;
            }

            sM[i][c0 + 0] = ev.x;   // in-place: this thread was the only reader
            sM[i][c0 + 1] = ev.y;
            sM[i][c0 + 2] = ev.z;
            sM[i][c0 + 3] = ev.w;

            __stcs((float4*)(O + (size_t)(rowA + i) * NDIM + colA + c0), ev);
        }

        // Transposed write of tile (J,I) — identical values by symmetry.
        if (I != J) {
            __syncthreads();
#pragma unroll
            for (int k = 0; k < 4; ++k) {
                const int jj = ty + 16 * k;
                float4 ev;
                ev.x = sM[c0 + 0][jj];
                ev.y = sM[c0 + 1][jj];
                ev.z = sM[c0 + 2][jj];
                ev.w = sM[c0 + 3][jj];
                __stcs((float4*)(O + (size_t)(colA + jj) * NDIM + rowA + c0), ev);
            }
        } else {
            __syncthreads();   // keep barrier count uniform across the block
        }
    }
}

extern "C" void kernel_launch(void* const* d_in, const int* in_sizes, int n_in,
                              void* d_out, int out_size) {
    const float* S = (const float*)d_in[0];
    float* O = (float*)d_out;

    fused_kernel<<<GRID, 256>>>(S, O);
}

// round 11
// speedup vs baseline: 1.0828x; 1.0828x over previous
#include <cuda_runtime.h>
#include <cuda_bf16.h>
#include <cstddef>
#include <cstdint>
#include <math.h>

#define NDIM 8192
#define NGROUP 32
#define GSIZE 256
#define INV_TAU 10.0f
#define TILE 64
#define NT (NDIM / TILE)          // 128 tiles per side
#define NPAIR (NT * (NT + 1) / 2) // 8256 tile pairs (I <= J)

#define ROWS_PB 4                 // rows per stats block
#define GRID1 (NDIM / ROWS_PB)    // 2048 stats blocks
#define ROW_BYTES (NDIM * 4)      // 32768 bytes per row

// Per-(row, group) softmax normalizer: 1 / sum(exp(x * 10)), NO max shift.
// Safe: x ~ N(0,1) so x*10 < ~60 << 88.7 (fp32 exp overflow).
__device__ float g_r[NDIM * NGROUP];

__device__ __forceinline__ uint32_t smem_u32(const void* p) {
    uint32_t a;
    asm("{ .reg .u64 t; cvta.to.shared.u64 t, %1; cvt.u32.u64 %0, t; }"
        : "=r"(a) : "l"(p));
    return a;
}

__device__ __forceinline__ void mbar_wait(uint32_t mbar, uint32_t parity) {
    asm volatile(
        "{\n\t"
        ".reg .pred P1;\n\t"
        "WL_%=:\n\t"
        "mbarrier.try_wait.parity.acquire.cta.shared::cta.b64 P1, [%0], %1, 0x989680;\n\t"
        "@P1 bra.uni WD_%=;\n\t"
        "bra.uni WL_%=;\n\t"
        "WD_%=:\n\t"
        "}"
        :: "r"(mbar), "r"(parity) : "memory");
}

// ---------------------------------------------------------------------------
// Kernel 1: per-(row, group) sum of exp(x*10) — TMA bulk-copy edition.
// Six warp-LDG variants all pinned at ~5.2 TB/s; this changes the MECHANISM:
// one cp.async.bulk per 32KB row into smem (mbarrier-tracked), next row
// prefetched while current computes (2-buffer pipeline, 4 rows/block).
// TMA bypasses the per-warp LDG issue path entirely and reaches the 6300
// B/cyc chip cap per B300 measurements. Compute reads smem with the
// conflict-free R6 mapping (warp w -> 4KB span, lane-consecutive float4).
// ---------------------------------------------------------------------------
__global__ __launch_bounds__(256) void stats_kernel(const float* __restrict__ S) {
    extern __shared__ float buf[];                   // 2 x 8192 floats
    __shared__ __align__(8) unsigned long long mbar[2];

    const int t    = threadIdx.x;
    const int warp = t >> 5;
    const int lane = t & 31;
    const uint32_t mb  = smem_u32(&mbar[0]);
    const uint32_t bsm = smem_u32(&buf[0]);

    if (t == 0) {
        asm volatile("mbarrier.init.shared.b64 [%0], 1;" :: "r"(mb));
        asm volatile("mbarrier.init.shared.b64 [%0], 1;" :: "r"(mb + 8));
    }
    __syncthreads();

    const int row0  = blockIdx.x * ROWS_PB;
    const int wbase = warp * (4 * GSIZE);            // float offset of warp span

    // Kick off row 0 into buffer 0.
    if (t == 0) {
        asm volatile("mbarrier.arrive.expect_tx.shared.b64 _, [%0], %1;"
                     :: "r"(mb), "r"(ROW_BYTES));
        asm volatile(
            "cp.async.bulk.shared::cta.global.mbarrier::complete_tx::bytes "
            "[%0], [%1], %2, [%3];"
            :: "r"(bsm), "l"(S + (size_t)row0 * NDIM), "r"(ROW_BYTES), "r"(mb)
            : "memory");
    }

    int ph0 = 0, ph1 = 0;
#pragma unroll
    for (int s = 0; s < ROWS_PB; ++s) {
        const int b = s & 1;

        // Prefetch row s+1 into the other buffer (free since iter s-1's sync).
        if (s + 1 < ROWS_PB && t == 0) {
            const int nb = (s + 1) & 1;
            asm volatile("mbarrier.arrive.expect_tx.shared.b64 _, [%0], %1;"
                         :: "r"(mb + 8 * nb), "r"(ROW_BYTES));
            asm volatile(
                "cp.async.bulk.shared::cta.global.mbarrier::complete_tx::bytes "
                "[%0], [%1], %2, [%3];"
                :: "r"(bsm + nb * ROW_BYTES),
                   "l"(S + (size_t)(row0 + s + 1) * NDIM),
                   "r"(ROW_BYTES), "r"(mb + 8 * nb)
                : "memory");
        }

        // Wait for buffer b.
        if (b == 0) { mbar_wait(mb, ph0);     ph0 ^= 1; }
        else        { mbar_wait(mb + 8, ph1); ph1 ^= 1; }

        const int row = row0 + s;
        const float* p = buf + b * NDIM + wbase + lane * 4;

        float4 v[8];
#pragma unroll
        for (int k = 0; k < 8; ++k)
            v[k] = *(const float4*)(p + k * 128);    // conflict-free LDS.128

        const int d0 = row - (wbase + lane * 4);     // diag pos rel. to lane base

        float part[4];
#pragma unroll
        for (int gg = 0; gg < 4; ++gg) {
            float ssum = 0.f;
#pragma unroll
            for (int h = 0; h < 2; ++h) {
                const int k  = 2 * gg + h;
                const int kb = k * 128;
                float ex = (d0 == kb + 0) ? 0.f : __expf(v[k].x * INV_TAU);
                float ey = (d0 == kb + 1) ? 0.f : __expf(v[k].y * INV_TAU);
                float ez = (d0 == kb + 2) ? 0.f : __expf(v[k].z * INV_TAU);
                float ew = (d0 == kb + 3) ? 0.f : __expf(v[k].w * INV_TAU);
                ssum += (ex + ey) + (ez + ew);
            }
            part[gg] = ssum;
        }

#pragma unroll
        for (int o = 16; o > 0; o >>= 1) {
#pragma unroll
            for (int gg = 0; gg < 4; ++gg)
                part[gg] += __shfl_xor_sync(0xffffffffu, part[gg], o);
        }

        if (lane == 0) {
            float4 r;
            r.x = 1.0f / part[0];
            r.y = 1.0f / part[1];
            r.z = 1.0f / part[2];
            r.w = 1.0f / part[3];
            *(float4*)&g_r[row * NGROUP + warp * 4] = r;   // 16B-aligned
        }

        __syncthreads();   // all reads of buffer b done before refill at s+2
    }
}

// ---------------------------------------------------------------------------
// Kernel 2 (unchanged — best measured form, ~6.3 TB/s effective, at cap).
// out[i,j] = bh[i,j] * bh[j,i]; one block per tile PAIR (I,J), I <= J,
// reversed order for L2 reuse of the stats pass's tail. A tile in registers;
// B staged transposed in smem; e overwrites b in place; symmetric 2x store.
//   e(i,j) = (exp(a*10) * rA[i]) * (exp(b*10) * rB[j])
// ---------------------------------------------------------------------------
__global__ __launch_bounds__(256, 6) void pair_kernel(const float* __restrict__ S,
                                                      float* __restrict__ O) {
    const int L = NPAIR - 1 - blockIdx.x;
    int J = (int)((sqrtf(8.0f * (float)L + 1.0f) - 1.0f) * 0.5f);
    while ((J + 1) * (J + 2) / 2 <= L) ++J;
    while (J * (J + 1) / 2 > L) --J;
    const int I = L - J * (J + 1) / 2;

    __shared__ float sM[TILE][TILE + 1];    // b-transposed, then e in place
    __shared__ float rA[TILE], rB[TILE];

    const int t  = threadIdx.x;
    const int tx = t & 15, ty = t >> 4;
    const int rowA = I * TILE, colA = J * TILE;
    const int c0 = tx * 4;

    float4 a4[4], b4[4];
#pragma unroll
    for (int k = 0; k < 4; ++k) {
        const int r = ty + 16 * k;
        a4[k] = __ldcs((const float4*)(S + (size_t)(rowA + r) * NDIM + colA + c0));
        b4[k] = __ldcs((const float4*)(S + (size_t)(colA + r) * NDIM + rowA + c0));
    }

    if (t < TILE) {
        rA[t] = g_r[(size_t)(rowA + t) * NGROUP + (colA >> 8)];
    } else if (t < 2 * TILE) {
        const int tt = t - TILE;
        rB[tt] = g_r[(size_t)(colA + tt) * NGROUP + (rowA >> 8)];
    }

#pragma unroll
    for (int k = 0; k < 4; ++k) {
        const int r = ty + 16 * k;
        sM[c0 + 0][r] = b4[k].x;
        sM[c0 + 1][r] = b4[k].y;
        sM[c0 + 2][r] = b4[k].z;
        sM[c0 + 3][r] = b4[k].w;
    }
    __syncthreads();

    const float4 rB4 = *(const float4*)&rB[c0];

#pragma unroll
    for (int k = 0; k < 4; ++k) {
        const int i = ty + 16 * k;
        const float ra = rA[i];

        float4 ev;
        ev.x = (__expf(a4[k].x * INV_TAU) * ra) * (__expf(sM[i][c0 + 0] * INV_TAU) * rB4.x);
        ev.y = (__expf(a4[k].y * INV_TAU) * ra) * (__expf(sM[i][c0 + 1] * INV_TAU) * rB4.y);
        ev.z = (__expf(a4[k].z * INV_TAU) * ra) * (__expf(sM[i][c0 + 2] * INV_TAU) * rB4.z);
        ev.w = (__expf(a4[k].w * INV_TAU) * ra) * (__expf(sM[i][c0 + 3] * INV_TAU) * rB4.w);

        if (I == J) {
            if (i == c0 + 0) ev.x = 0.f;
            if (i == c0 + 1) ev.y = 0.f;
            if (i == c0 + 2) ev.z = 0.f;
            if (i == c0 + 3) ev.w = 0.f;
        }

        sM[i][c0 + 0] = ev.x;
        sM[i][c0 + 1] = ev.y;
        sM[i][c0 + 2] = ev.z;
        sM[i][c0 + 3] = ev.w;

        __stcs((float4*)(O + (size_t)(rowA + i) * NDIM + colA + c0), ev);
    }

    if (I != J) {
        __syncthreads();
#pragma unroll
        for (int k = 0; k < 4; ++k) {
            const int jj = ty + 16 * k;
            float4 ev;
            ev.x = sM[c0 + 0][jj];
            ev.y = sM[c0 + 1][jj];
            ev.z = sM[c0 + 2][jj];
            ev.w = sM[c0 + 3][jj];
            __stcs((float4*)(O + (size_t)(colA + jj) * NDIM + rowA + c0), ev);
        }
    }
}

extern "C" void kernel_launch(void* const* d_in, const int* in_sizes, int n_in,
                              void* d_out, int out_size) {
    const float* S = (const float*)d_in[0];
    float* O = (float*)d_out;

    const int smem = 2 * ROW_BYTES;   // 64 KB double buffer
    cudaFuncSetAttribute(stats_kernel,
                         cudaFuncAttributeMaxDynamicSharedMemorySize, smem);

    stats_kernel<<<GRID1, 256, smem>>>(S);
    pair_kernel<<<NPAIR, 256>>>(S, O);
}